// round 1
// baseline (speedup 1.0000x reference)
#include <cuda_runtime.h>
#include <cuda_bf16.h>
#include <cstdint>

// Problem constants (fixed by the dataset)
#define Bn 16384
#define Dn 2048
#define Hn 512
#define BDn ((size_t)Bn * (size_t)Dn)

// Scratch (device globals — no allocations allowed)
__device__ int   g_k[Bn];
__device__ float g_l1[Bn];

// ---------------------------------------------------------------------------
// Kernel A: fused predictor.
//   h = relu(x @ W1 + b1);  logit = h @ W2 + b2;  sig = sigmoid(logit)
//   sparsity = 0.05 + 0.25*sig;  k = max(1, rint(2048*(1-sparsity)))
// One CTA = 64 rows x all 512 columns. 512 threads: thread j owns column j,
// 64 row-accumulators packed as 32 f32x2 (fma.rn.f32x2 = 2x FFMA throughput).
// ---------------------------------------------------------------------------
__global__ __launch_bounds__(512, 1)
void predictor_kernel(const float* __restrict__ x,
                      const float* __restrict__ W1,
                      const float* __restrict__ b1,
                      const float* __restrict__ W2,
                      const float* __restrict__ b2,
                      float* __restrict__ out_sparsity,  // d_out + 2*BD
                      int* __restrict__ gk)
{
    __shared__ __align__(16) float xs[16][66];   // [k][row], stride 66 (8B-aligned rows)
    __shared__ float red[16][64];                // per-warp partials for row reduction

    const int j  = threadIdx.x;                  // column 0..511
    const int m0 = blockIdx.x * 64;

    // x-tile load mapping: 64 rows x 16 k per chunk; thread loads one float2
    const int lrow = j >> 3;                     // 0..63
    const int lk   = (j & 7) * 2;                // 0,2,...,14
    const float* xrow = x + (size_t)(m0 + lrow) * Dn + lk;

    unsigned long long acc[32];
#pragma unroll
    for (int i = 0; i < 32; i++) acc[i] = 0ULL;

    float2 cur = *(const float2*)xrow;           // chunk 0 prefetch

    for (int c = 0; c < 128; c++) {
        xs[lk][lrow]     = cur.x;
        xs[lk + 1][lrow] = cur.y;
        __syncthreads();

        if (c < 127) cur = *(const float2*)(xrow + (size_t)(c + 1) * 16);

        // W1 chunk for this thread's column (L2-resident, reused by all CTAs)
        float w[16];
#pragma unroll
        for (int kk = 0; kk < 16; kk++)
            w[kk] = __ldg(&W1[(size_t)(c * 16 + kk) * Hn + j]);

#pragma unroll
        for (int kk = 0; kk < 16; kk++) {
            unsigned long long w2;
            asm("mov.b64 %0, {%1, %1};" : "=l"(w2) : "f"(w[kk]));
            const unsigned long long* xsq =
                reinterpret_cast<const unsigned long long*>(&xs[kk][0]);
#pragma unroll
            for (int r = 0; r < 32; r++) {
                unsigned long long xv = xsq[r];  // rows {2r, 2r+1}, broadcast LDS.64
                asm("fma.rn.f32x2 %0, %1, %2, %0;" : "+l"(acc[r]) : "l"(xv), "l"(w2));
            }
        }
        __syncthreads();
    }

    // Epilogue: relu, scale by W2, reduce over j per row (deterministic order).
    const float b1j = b1[j];
    const float w2j = W2[j];
    const int lane = j & 31, wid = j >> 5;

#pragma unroll
    for (int r = 0; r < 32; r++) {
        float a0, a1;
        asm("mov.b64 {%0, %1}, %2;" : "=f"(a0), "=f"(a1) : "l"(acc[r]));
        float p0 = fmaxf(a0 + b1j, 0.f) * w2j;
        float p1 = fmaxf(a1 + b1j, 0.f) * w2j;
#pragma unroll
        for (int o = 16; o > 0; o >>= 1) {
            p0 += __shfl_down_sync(0xffffffffu, p0, o);
            p1 += __shfl_down_sync(0xffffffffu, p1, o);
        }
        if (lane == 0) { red[wid][2 * r] = p0; red[wid][2 * r + 1] = p1; }
    }
    __syncthreads();

    if (j < 64) {
        float s = 0.f;
#pragma unroll
        for (int q = 0; q < 16; q++) s += red[q][j];
        float logit = s + b2[0];
        float sig = 1.f / (1.f + expf(-logit));
        float sp  = 0.05f + 0.25f * sig;
        float kf  = 2048.f * (1.f - sp);
        int k = (int)rintf(kf);                  // round-half-even, matches jnp.round
        if (k < 1) k = 1;
        int row = m0 + j;
        out_sparsity[row] = sp;
        gk[row] = k;
    }
}

// ---------------------------------------------------------------------------
// Kernel B: per-row exact k-th smallest |x| via 4-pass radix select on float
// bits, then mask/sparse_x/actual_sparsity/l1-row outputs.
// One CTA per row, 256 threads, 8 elements/thread (register-resident).
// ---------------------------------------------------------------------------
__global__ __launch_bounds__(256)
void select_kernel(const float* __restrict__ x,
                   const int* __restrict__ gk,
                   float* __restrict__ out,     // d_out base
                   float* __restrict__ gl1)
{
    __shared__ int hist[256];
    __shared__ int warpsum[8];
    __shared__ int warpoff[8];
    __shared__ int s_bin, s_rem;
    __shared__ int scnt[8];
    __shared__ float sl1[8];

    const int r = blockIdx.x;
    const int t = threadIdx.x;
    const float* xr = x + (size_t)r * Dn;

    float    xv[8];
    unsigned kb[8];
#pragma unroll
    for (int i = 0; i < 8; i++) {
        xv[i] = xr[t + 256 * i];
        kb[i] = __float_as_uint(fabsf(xv[i]));   // |x|>=0 -> uint order == float order
    }

    int kt = gk[r];
    unsigned prefix = 0, himask = 0;

#pragma unroll
    for (int p = 3; p >= 0; p--) {
        const int shift = p * 8;
        hist[t] = 0;
        __syncthreads();

#pragma unroll
        for (int i = 0; i < 8; i++) {
            unsigned key = kb[i];
            bool act = ((key & himask) == prefix);
            int bin = act ? (int)((key >> shift) & 0xFF) : -1;
            unsigned grp = __match_any_sync(0xffffffffu, bin);
            int leader = __ffs(grp) - 1;
            if (act && (t & 31) == leader) atomicAdd(&hist[bin], __popc(grp));
        }
        __syncthreads();

        // block inclusive scan of 256 bins
        int c = hist[t];
        int v = c;
        const int lane = t & 31, w = t >> 5;
#pragma unroll
        for (int o = 1; o < 32; o <<= 1) {
            int n = __shfl_up_sync(0xffffffffu, v, o);
            if (lane >= o) v += n;
        }
        if (lane == 31) warpsum[w] = v;
        __syncthreads();
        if (t == 0) {
            int run = 0;
#pragma unroll
            for (int q = 0; q < 8; q++) { warpoff[q] = run; run += warpsum[q]; }
        }
        __syncthreads();
        int incl = v + warpoff[w];
        int excl = incl - c;
        if (excl < kt && incl >= kt) { s_bin = t; s_rem = kt - excl; }
        __syncthreads();

        prefix |= ((unsigned)s_bin) << shift;
        kt = s_rem;
        himask |= 0xFFu << shift;
        __syncthreads();
    }

    const unsigned thr = prefix;                 // exact bits of k-th smallest |x|
    int cnt = 0;
    float l1 = 0.f;
    const size_t base = (size_t)r * Dn;
#pragma unroll
    for (int i = 0; i < 8; i++) {
        bool keep = kb[i] > thr;                 // strict >, matches reference
        size_t idx = base + (size_t)(t + 256 * i);
        out[idx]       = keep ? xv[i] : 0.f;                 // sparse_x
        out[BDn + idx] = keep ? 1.f : 0.f;                   // mask
        cnt += keep ? 1 : 0;
        l1  += keep ? __uint_as_float(kb[i]) : 0.f;
    }

    const int lane = t & 31, w = t >> 5;
#pragma unroll
    for (int o = 16; o > 0; o >>= 1) {
        cnt += __shfl_down_sync(0xffffffffu, cnt, o);
        l1  += __shfl_down_sync(0xffffffffu, l1, o);
    }
    if (lane == 0) { scnt[w] = cnt; sl1[w] = l1; }
    __syncthreads();
    if (t == 0) {
        int C = 0; float L = 0.f;
#pragma unroll
        for (int q = 0; q < 8; q++) { C += scnt[q]; L += sl1[q]; }
        out[2 * BDn + Bn + r] = (float)C * (1.0f / 2048.0f);  // actual_sparsity
        gl1[r] = L;
    }
}

// ---------------------------------------------------------------------------
// Kernel C: deterministic mean of per-row L1 sums.
// ---------------------------------------------------------------------------
__global__ __launch_bounds__(256)
void l1_reduce_kernel(const float* __restrict__ gl1, float* __restrict__ out_l1)
{
    __shared__ double sd[256];
    const int t = threadIdx.x;
    double s = 0.0;
    for (int i = t; i < Bn; i += 256) s += (double)gl1[i];
    sd[t] = s;
    __syncthreads();
#pragma unroll
    for (int off = 128; off > 0; off >>= 1) {
        if (t < off) sd[t] += sd[t + off];
        __syncthreads();
    }
    if (t == 0) out_l1[0] = (float)(sd[0] / (double)Bn);
}

// ---------------------------------------------------------------------------
extern "C" void kernel_launch(void* const* d_in, const int* in_sizes, int n_in,
                              void* d_out, int out_size)
{
    const float* x  = (const float*)d_in[0];
    const float* W1 = (const float*)d_in[1];
    const float* b1 = (const float*)d_in[2];
    const float* W2 = (const float*)d_in[3];
    const float* b2 = (const float*)d_in[4];
    float* out = (float*)d_out;

    int* gk; float* gl1;
    cudaGetSymbolAddress((void**)&gk,  g_k);
    cudaGetSymbolAddress((void**)&gl1, g_l1);

    predictor_kernel<<<Bn / 64, 512>>>(x, W1, b1, W2, b2, out + 2 * BDn, gk);
    select_kernel<<<Bn, 256>>>(x, gk, out, gl1);
    l1_reduce_kernel<<<1, 256>>>(gl1, out + 2 * BDn + 2 * (size_t)Bn);
}

// round 3
// speedup vs baseline: 1.6675x; 1.6675x over previous
#include <cuda_runtime.h>
#include <cuda_bf16.h>
#include <cstdint>

// Problem constants (fixed by the dataset)
#define Bn 16384
#define Dn 2048
#define Hn 512
#define BDn ((size_t)Bn * (size_t)Dn)

// Scratch (device globals — no allocations allowed)
__device__ int   g_k[Bn];
__device__ float g_l1[Bn];

// ---------------------------------------------------------------------------
// Kernel A: fused predictor, register-tiled fp32 GEMM.
//   C[64 rows x 512 cols] per CTA, 512 threads, each thread an 8x8 fragment
//   (32 f32x2 accumulators, fma.rn.f32x2 = 2 FMA/inst).
//   Thread (ty = t>>6, tx = t&63): rows 8ty..8ty+7,
//   cols {4tx..4tx+3} U {256+4tx..256+4tx+3}  (conflict-free LDS.128).
//   Then relu, *W2, row-reduce, sigmoid -> sparsity + k.
//   (Resubmission of R2 kernel — R2 bench was an infra failure, never ran.)
// ---------------------------------------------------------------------------
__global__ __launch_bounds__(512, 1)
void predictor_kernel(const float* __restrict__ x,
                      const float* __restrict__ W1,
                      const float* __restrict__ b1,
                      const float* __restrict__ W2,
                      const float* __restrict__ b2,
                      float* __restrict__ out_sparsity,
                      int* __restrict__ gk)
{
    __shared__ __align__(16) float wsm[2][16][512];   // [buf][k][col]  32KB each
    __shared__ __align__(16) float xsm[2][16][64];    // [buf][k][row]   4KB each
    __shared__ float red[16][8];

    const int t  = threadIdx.x;
    const int tx = t & 63;
    const int ty = t >> 6;
    const int m0 = blockIdx.x * 64;

    // x-chunk load mapping: thread -> (row, 2 consecutive k)
    const int xrow = t >> 3;               // 0..63
    const int xk   = (t & 7) * 2;          // 0,2,...,14
    const float* xg = x + (size_t)(m0 + xrow) * Dn + xk;

    unsigned long long acc[8][4];
#pragma unroll
    for (int r = 0; r < 8; r++)
#pragma unroll
        for (int p = 0; p < 4; p++) acc[r][p] = 0ULL;

    float4 wreg[4];
    float2 xreg;

    // ---- prefetch + store chunk 0 ----
#pragma unroll
    for (int i = 0; i < 4; i++)
        wreg[i] = *(const float4*)&W1[(size_t)i * 2048 + 4 * t];
    xreg = *(const float2*)xg;
#pragma unroll
    for (int i = 0; i < 4; i++) {
        int o = i * 2048 + 4 * t;
        *(float4*)&wsm[0][o >> 9][o & 511] = wreg[i];
    }
    xsm[0][xk][xrow]     = xreg.x;
    xsm[0][xk + 1][xrow] = xreg.y;
    __syncthreads();

    for (int c = 0; c < 128; c++) {
        const int b = c & 1;
        // issue next chunk's global loads early (latency overlaps compute)
        if (c < 127) {
            const float* wg = W1 + (size_t)(c + 1) * 8192;
#pragma unroll
            for (int i = 0; i < 4; i++)
                wreg[i] = *(const float4*)&wg[i * 2048 + 4 * t];
            xreg = *(const float2*)(xg + (size_t)(c + 1) * 16);
        }

#pragma unroll
        for (int kk = 0; kk < 16; kk++) {
            ulonglong2 wa = *(const ulonglong2*)&wsm[b][kk][4 * tx];        // cols 4tx..4tx+3
            ulonglong2 wb = *(const ulonglong2*)&wsm[b][kk][256 + 4 * tx];  // cols 256+4tx..+3
            float4 xa = *(const float4*)&xsm[b][kk][8 * ty];                // rows 8ty..8ty+3 (bcast)
            float4 xb = *(const float4*)&xsm[b][kk][8 * ty + 4];            // rows +4..+7 (bcast)

            unsigned long long xd[8];
            asm("mov.b64 %0,{%1,%1};" : "=l"(xd[0]) : "f"(xa.x));
            asm("mov.b64 %0,{%1,%1};" : "=l"(xd[1]) : "f"(xa.y));
            asm("mov.b64 %0,{%1,%1};" : "=l"(xd[2]) : "f"(xa.z));
            asm("mov.b64 %0,{%1,%1};" : "=l"(xd[3]) : "f"(xa.w));
            asm("mov.b64 %0,{%1,%1};" : "=l"(xd[4]) : "f"(xb.x));
            asm("mov.b64 %0,{%1,%1};" : "=l"(xd[5]) : "f"(xb.y));
            asm("mov.b64 %0,{%1,%1};" : "=l"(xd[6]) : "f"(xb.z));
            asm("mov.b64 %0,{%1,%1};" : "=l"(xd[7]) : "f"(xb.w));

#pragma unroll
            for (int r = 0; r < 8; r++) {
                asm("fma.rn.f32x2 %0,%1,%2,%0;" : "+l"(acc[r][0]) : "l"(xd[r]), "l"(wa.x));
                asm("fma.rn.f32x2 %0,%1,%2,%0;" : "+l"(acc[r][1]) : "l"(xd[r]), "l"(wa.y));
                asm("fma.rn.f32x2 %0,%1,%2,%0;" : "+l"(acc[r][2]) : "l"(xd[r]), "l"(wb.x));
                asm("fma.rn.f32x2 %0,%1,%2,%0;" : "+l"(acc[r][3]) : "l"(xd[r]), "l"(wb.y));
            }
        }

        if (c < 127) {
            const int nb = b ^ 1;
#pragma unroll
            for (int i = 0; i < 4; i++) {
                int o = i * 2048 + 4 * t;
                *(float4*)&wsm[nb][o >> 9][o & 511] = wreg[i];
            }
            xsm[nb][xk][xrow]     = xreg.x;
            xsm[nb][xk + 1][xrow] = xreg.y;
        }
        __syncthreads();
    }

    // ---- epilogue: relu + *W2 + reduce over 512 cols per row ----
    float b1v[8], w2v[8];
#pragma unroll
    for (int q = 0; q < 4; q++) {
        b1v[q]     = __ldg(&b1[4 * tx + q]);
        b1v[4 + q] = __ldg(&b1[256 + 4 * tx + q]);
        w2v[q]     = __ldg(&W2[4 * tx + q]);
        w2v[4 + q] = __ldg(&W2[256 + 4 * tx + q]);
    }
    const int lane = t & 31, w = t >> 5;
#pragma unroll
    for (int r = 0; r < 8; r++) {
        float s = 0.f;
#pragma unroll
        for (int p = 0; p < 4; p++) {
            float lo, hi;
            asm("mov.b64 {%0,%1},%2;" : "=f"(lo), "=f"(hi) : "l"(acc[r][p]));
            s += fmaxf(lo + b1v[2 * p],     0.f) * w2v[2 * p];
            s += fmaxf(hi + b1v[2 * p + 1], 0.f) * w2v[2 * p + 1];
        }
#pragma unroll
        for (int o = 16; o > 0; o >>= 1)
            s += __shfl_down_sync(0xffffffffu, s, o);
        if (lane == 0) red[w][r] = s;     // warp w covers rows 8*(w>>1)..+7
    }
    __syncthreads();

    if (t < 64) {
        const int R = t;
        float s = red[2 * (R >> 3)][R & 7] + red[2 * (R >> 3) + 1][R & 7];
        float logit = s + b2[0];
        float sig = 1.f / (1.f + expf(-logit));
        float sp  = 0.05f + 0.25f * sig;
        float kf  = 2048.f * (1.f - sp);
        int k = (int)rintf(kf);            // half-even, matches jnp.round
        if (k < 1) k = 1;
        out_sparsity[m0 + R] = sp;
        gk[m0 + R] = k;
    }
}

// ---------------------------------------------------------------------------
// Kernel B: per-row exact k-th smallest |x| via 4-pass radix select on float
// bits, then mask/sparse_x/actual_sparsity/l1-row outputs. (unchanged)
// ---------------------------------------------------------------------------
__global__ __launch_bounds__(256)
void select_kernel(const float* __restrict__ x,
                   const int* __restrict__ gk,
                   float* __restrict__ out,
                   float* __restrict__ gl1)
{
    __shared__ int hist[256];
    __shared__ int warpsum[8];
    __shared__ int warpoff[8];
    __shared__ int s_bin, s_rem;
    __shared__ int scnt[8];
    __shared__ float sl1[8];

    const int r = blockIdx.x;
    const int t = threadIdx.x;
    const float* xr = x + (size_t)r * Dn;

    float    xv[8];
    unsigned kb[8];
#pragma unroll
    for (int i = 0; i < 8; i++) {
        xv[i] = xr[t + 256 * i];
        kb[i] = __float_as_uint(fabsf(xv[i]));
    }

    int kt = gk[r];
    unsigned prefix = 0, himask = 0;

#pragma unroll
    for (int p = 3; p >= 0; p--) {
        const int shift = p * 8;
        hist[t] = 0;
        __syncthreads();

#pragma unroll
        for (int i = 0; i < 8; i++) {
            unsigned key = kb[i];
            bool act = ((key & himask) == prefix);
            int bin = act ? (int)((key >> shift) & 0xFF) : -1;
            unsigned grp = __match_any_sync(0xffffffffu, bin);
            int leader = __ffs(grp) - 1;
            if (act && (t & 31) == leader) atomicAdd(&hist[bin], __popc(grp));
        }
        __syncthreads();

        int c = hist[t];
        int v = c;
        const int lane = t & 31, w = t >> 5;
#pragma unroll
        for (int o = 1; o < 32; o <<= 1) {
            int n = __shfl_up_sync(0xffffffffu, v, o);
            if (lane >= o) v += n;
        }
        if (lane == 31) warpsum[w] = v;
        __syncthreads();
        if (t == 0) {
            int run = 0;
#pragma unroll
            for (int q = 0; q < 8; q++) { warpoff[q] = run; run += warpsum[q]; }
        }
        __syncthreads();
        int incl = v + warpoff[w];
        int excl = incl - c;
        if (excl < kt && incl >= kt) { s_bin = t; s_rem = kt - excl; }
        __syncthreads();

        prefix |= ((unsigned)s_bin) << shift;
        kt = s_rem;
        himask |= 0xFFu << shift;
        __syncthreads();
    }

    const unsigned thr = prefix;
    int cnt = 0;
    float l1 = 0.f;
    const size_t base = (size_t)r * Dn;
#pragma unroll
    for (int i = 0; i < 8; i++) {
        bool keep = kb[i] > thr;
        size_t idx = base + (size_t)(t + 256 * i);
        out[idx]       = keep ? xv[i] : 0.f;
        out[BDn + idx] = keep ? 1.f : 0.f;
        cnt += keep ? 1 : 0;
        l1  += keep ? __uint_as_float(kb[i]) : 0.f;
    }

    const int lane = t & 31, w = t >> 5;
#pragma unroll
    for (int o = 16; o > 0; o >>= 1) {
        cnt += __shfl_down_sync(0xffffffffu, cnt, o);
        l1  += __shfl_down_sync(0xffffffffu, l1, o);
    }
    if (lane == 0) { scnt[w] = cnt; sl1[w] = l1; }
    __syncthreads();
    if (t == 0) {
        int C = 0; float L = 0.f;
#pragma unroll
        for (int q = 0; q < 8; q++) { C += scnt[q]; L += sl1[q]; }
        out[2 * BDn + Bn + r] = (float)C * (1.0f / 2048.0f);
        gl1[r] = L;
    }
}

// ---------------------------------------------------------------------------
// Kernel C: deterministic mean of per-row L1 sums.
// ---------------------------------------------------------------------------
__global__ __launch_bounds__(256)
void l1_reduce_kernel(const float* __restrict__ gl1, float* __restrict__ out_l1)
{
    __shared__ double sd[256];
    const int t = threadIdx.x;
    double s = 0.0;
    for (int i = t; i < Bn; i += 256) s += (double)gl1[i];
    sd[t] = s;
    __syncthreads();
#pragma unroll
    for (int off = 128; off > 0; off >>= 1) {
        if (t < off) sd[t] += sd[t + off];
        __syncthreads();
    }
    if (t == 0) out_l1[0] = (float)(sd[0] / (double)Bn);
}

// ---------------------------------------------------------------------------
extern "C" void kernel_launch(void* const* d_in, const int* in_sizes, int n_in,
                              void* d_out, int out_size)
{
    const float* x  = (const float*)d_in[0];
    const float* W1 = (const float*)d_in[1];
    const float* b1 = (const float*)d_in[2];
    const float* W2 = (const float*)d_in[3];
    const float* b2 = (const float*)d_in[4];
    float* out = (float*)d_out;

    int* gk; float* gl1;
    cudaGetSymbolAddress((void**)&gk,  g_k);
    cudaGetSymbolAddress((void**)&gl1, g_l1);

    predictor_kernel<<<Bn / 64, 512>>>(x, W1, b1, W2, b2, out + 2 * BDn, gk);
    select_kernel<<<Bn, 256>>>(x, gk, out, gl1);
    l1_reduce_kernel<<<1, 256>>>(gl1, out + 2 * BDn + 2 * (size_t)Bn);
}